// round 3
// baseline (speedup 1.0000x reference)
#include <cuda_runtime.h>
#include <cuda_fp16.h>
#include <math.h>

#define NN 100000
#define EE 1600000
#define KE 64
#define INC 128
#define HID 256
#define OC 16

// ---- static device scratch ----
__device__ __half  g_Wh[(size_t)NN * KE];  // MLP_W^T fp16 [N,64]
__device__ float   g_S [(size_t)NN * KE];  // S fp32
__device__ __half  g_Sh[(size_t)NN * KE];  // S fp16 (SpMM2 gather)
__device__ int     g_deg[NN];
__device__ int     g_ptr[NN + 1];
__device__ int     g_pos[NN];
__device__ int     g_srt[EE];
__device__ int     g_bsum[128];
__device__ float   g_SS[KE * KE];
__device__ float   g_Wc[OC * INC];
__device__ float   g_bc[OC];
__device__ double  g_cut;
__device__ double  g_dt;

#define TRB 6250          // transpose blocks (3125 x 2)
#define HIB 6250          // hist blocks
#define WCB 8             // wcomb blocks
#define SP2B 12500        // spmm2 blocks (8 warps each)
#define SSB 592           // SSmat blocks
#define FINB 6250         // final blocks

// ================================================================ mega1: transpose | hist | wcomb
__global__ void __launch_bounds__(256) k_mega1(const float* __restrict__ W,
                                               const int* __restrict__ col,
                                               const float* __restrict__ finW,
                                               const float* __restrict__ mlpxW,
                                               const float* __restrict__ mlpxb,
                                               const float* __restrict__ finb) {
    int b = blockIdx.x;
    int t = threadIdx.x;
    if (b < HIB) {                                   // ---- hist (first: longest pole)
        int e = b * 256 + t;
        atomicAdd(&g_deg[col[e]], 1);
    } else if (b < HIB + TRB) {                      // ---- transpose -> fp16
        __shared__ float tile[32][33];
        int tb = b - HIB;
        int v0 = (tb % 3125) * 32, k0 = (tb / 3125) * 32;
        int tx = t & 31, ty = t >> 5;                // 32 x 8
        #pragma unroll
        for (int r = ty; r < 32; r += 8)
            tile[r][tx] = W[(size_t)(k0 + r) * NN + v0 + tx];
        __syncthreads();
        #pragma unroll
        for (int r = ty; r < 32; r += 8)
            g_Wh[(size_t)(v0 + r) * KE + k0 + tx] = __float2half(tile[tx][r]);
    } else {                                         // ---- wcomb
        int idx = (b - HIB - TRB) * 256 + t;
        if (idx < OC * INC) {
            int o = idx / INC, c = idx % INC;
            float s = 0.f;
            for (int h = 0; h < HID; h++) s += finW[o * 320 + h] * mlpxW[h * INC + c];
            g_Wc[o * INC + c] = s;
        }
        if (idx < OC) {
            float s = finb[idx];
            for (int h = 0; h < HID; h++) s += finW[idx * 320 + h] * mlpxb[h];
            g_bc[idx] = s;
        }
    }
}

// ================================================================ scan1 (+ zero SS/cut/dt)
__global__ void k_scan1() {
    __shared__ int sh[256];
    int t = threadIdx.x;
    if (blockIdx.x == 0) {                 // opportunistic zeroing (needed only before mega2)
        for (int i = t; i < KE * KE; i += 256) g_SS[i] = 0.f;
        if (t == 0) { g_cut = 0.0; g_dt = 0.0; }
    }
    int base = blockIdx.x * 1024 + t * 4;
    int v0 = (base + 0 < NN) ? g_deg[base + 0] : 0;
    int v1 = (base + 1 < NN) ? g_deg[base + 1] : 0;
    int v2 = (base + 2 < NN) ? g_deg[base + 2] : 0;
    int v3 = (base + 3 < NN) ? g_deg[base + 3] : 0;
    int s = v0 + v1 + v2 + v3;
    sh[t] = s; __syncthreads();
    for (int off = 1; off < 256; off <<= 1) {
        int x = (t >= off) ? sh[t - off] : 0;
        __syncthreads();
        sh[t] += x;
        __syncthreads();
    }
    int run = sh[t] - s;
    if (t == 255) g_bsum[blockIdx.x] = sh[255];
    if (base + 0 < NN) g_ptr[base + 0] = run; run += v0;
    if (base + 1 < NN) g_ptr[base + 1] = run; run += v1;
    if (base + 2 < NN) g_ptr[base + 2] = run; run += v2;
    if (base + 3 < NN) g_ptr[base + 3] = run;
}

// ================================================================ scan23: block-sum scan (redundant per block) + apply
__global__ void k_scan23(int nblk) {
    __shared__ int sinc[128];   // inclusive
    __shared__ int sexc[128];   // exclusive
    int t = threadIdx.x;
    if (t < 128) {
        int v = (t < nblk) ? g_bsum[t] : 0;
        sinc[t] = v;
    }
    __syncthreads();
    for (int off = 1; off < 128; off <<= 1) {
        int x = 0;
        if (t < 128 && t >= off) x = sinc[t - off];
        __syncthreads();
        if (t < 128) sinc[t] += x;
        __syncthreads();
    }
    if (t < 128) sexc[t] = sinc[t] - ((t < nblk) ? g_bsum[t] : 0);
    __syncthreads();
    int i = blockIdx.x * blockDim.x + t;
    if (i < NN) {
        int p = g_ptr[i] + sexc[i >> 10];
        g_ptr[i] = p;
        g_pos[i] = p;
    }
    if (i == 0) g_ptr[NN] = EE;
}

// ================================================================ scatter edges into CSR
__global__ void k_scatter(const int* __restrict__ row, const int* __restrict__ col) {
    int e = blockIdx.x * blockDim.x + threadIdx.x;
    if (e < EE) {
        int p = atomicAdd(&g_pos[col[e]], 1);
        g_srt[p] = row[e];
    }
}

// ================================================================ SpMM1 + softmax + deg_term (warp/node)
__global__ void __launch_bounds__(256) k_spmm1(const float* __restrict__ bias) {
    __shared__ double sdt[8];
    int w = (blockIdx.x * blockDim.x + threadIdx.x) >> 5;
    int l = threadIdx.x & 31, wl = threadIdx.x >> 5;
    int s = g_ptr[w], e = g_ptr[w + 1];
    const __half2* F = (const __half2*)g_Wh;
    float a0 = 0.f, a1 = 0.f;
    int i = s;
    for (; i + 4 <= e; i += 4) {
        int s0 = __ldg(&g_srt[i]),     s1 = __ldg(&g_srt[i + 1]);
        int s2 = __ldg(&g_srt[i + 2]), s3 = __ldg(&g_srt[i + 3]);
        float2 f0 = __half22float2(__ldg(&F[(size_t)s0 * 32 + l]));
        float2 f1 = __half22float2(__ldg(&F[(size_t)s1 * 32 + l]));
        float2 f2 = __half22float2(__ldg(&F[(size_t)s2 * 32 + l]));
        float2 f3 = __half22float2(__ldg(&F[(size_t)s3 * 32 + l]));
        a0 += (f0.x + f1.x) + (f2.x + f3.x);
        a1 += (f0.y + f1.y) + (f2.y + f3.y);
    }
    for (; i < e; i++) {
        int s0 = __ldg(&g_srt[i]);
        float2 f = __half22float2(__ldg(&F[(size_t)s0 * 32 + l]));
        a0 += f.x; a1 += f.y;
    }
    float2 b = __ldg(&((const float2*)bias)[l]);
    a0 += b.x; a1 += b.y;
    float m = fmaxf(a0, a1);
    #pragma unroll
    for (int d = 16; d >= 1; d >>= 1) m = fmaxf(m, __shfl_xor_sync(0xffffffffu, m, d));
    float e0 = expf(a0 - m), e1 = expf(a1 - m);
    float sum = e0 + e1;
    #pragma unroll
    for (int d = 16; d >= 1; d >>= 1) sum += __shfl_xor_sync(0xffffffffu, sum, d);
    float inv = 1.f / sum;
    float s0 = e0 * inv, s1 = e1 * inv;
    ((float2*)g_S)[(size_t)w * 32 + l] = make_float2(s0, s1);
    ((__half2*)g_Sh)[(size_t)w * 32 + l] = __floats2half2_rn(s0, s1);
    float ssq = s0 * s0 + s1 * s1;
    #pragma unroll
    for (int d = 16; d >= 1; d >>= 1) ssq += __shfl_xor_sync(0xffffffffu, ssq, d);
    if (l == 0) sdt[wl] = (double)(e - s) * (double)ssq;
    __syncthreads();
    if (threadIdx.x == 0) {
        double t = 0.0;
        #pragma unroll
        for (int q = 0; q < 8; q++) t += sdt[q];
        atomicAdd(&g_dt, t);
    }
}

// ================================================================ mega2: spmm2 | SSmat | final
__global__ void __launch_bounds__(256) k_mega2(const float* __restrict__ x,
                                               const float* __restrict__ finW,
                                               float* __restrict__ out) {
    __shared__ double sred[8];
    __shared__ float4 stile[16][16];     // SSmat rows  (4KB)
    __shared__ float4 sWx[32][16];       // final Wx    (8KB)
    __shared__ float4 sWa[16][16];       // final Wa    (4KB)
    __shared__ float  sbo[16];
    int b = blockIdx.x;
    int t = threadIdx.x;

    if (b < SP2B) {
        // ---------------- spmm2 + cut ----------------
        int w = b * 8 + (t >> 5);
        int l = t & 31, wl = t >> 5;
        int s = g_ptr[w], e = g_ptr[w + 1];
        const __half2* F = (const __half2*)g_Sh;
        float a0 = 0.f, a1 = 0.f;
        int i = s;
        for (; i + 4 <= e; i += 4) {
            int s0 = __ldg(&g_srt[i]),     s1 = __ldg(&g_srt[i + 1]);
            int s2 = __ldg(&g_srt[i + 2]), s3 = __ldg(&g_srt[i + 3]);
            float2 f0 = __half22float2(__ldg(&F[(size_t)s0 * 32 + l]));
            float2 f1 = __half22float2(__ldg(&F[(size_t)s1 * 32 + l]));
            float2 f2 = __half22float2(__ldg(&F[(size_t)s2 * 32 + l]));
            float2 f3 = __half22float2(__ldg(&F[(size_t)s3 * 32 + l]));
            a0 += (f0.x + f1.x) + (f2.x + f3.x);
            a1 += (f0.y + f1.y) + (f2.y + f3.y);
        }
        for (; i < e; i++) {
            int s0 = __ldg(&g_srt[i]);
            float2 f = __half22float2(__ldg(&F[(size_t)s0 * 32 + l]));
            a0 += f.x; a1 += f.y;
        }
        float2 sc = ((const float2*)g_S)[(size_t)w * 32 + l];
        float dot = a0 * sc.x + a1 * sc.y;
        #pragma unroll
        for (int d = 16; d >= 1; d >>= 1) dot += __shfl_xor_sync(0xffffffffu, dot, d);
        if (l == 0) sred[wl] = (double)dot;
        __syncthreads();
        if (t == 0) {
            double acc = 0.0;
            #pragma unroll
            for (int q = 0; q < 8; q++) acc += sred[q];
            atomicAdd(&g_cut, acc);
        }
    } else if (b < SP2B + SSB) {
        // ---------------- SS = S^T S ----------------
        int bb = b - SP2B;
        int ti = t >> 4, tj = t & 15;
        float acc[4][4] = {};
        int chunk = (NN + SSB - 1) / SSB;
        int r0 = bb * chunk;
        int r1 = min(r0 + chunk, NN);
        const float4* S4 = (const float4*)g_S;
        for (int rb = r0; rb < r1; rb += 16) {
            int nr = min(16, r1 - rb);
            if (t < nr * 16) stile[t >> 4][t & 15] = S4[(size_t)(rb + (t >> 4)) * 16 + (t & 15)];
            __syncthreads();
            for (int r = 0; r < nr; r++) {
                float4 a = stile[r][ti];
                float4 c = stile[r][tj];
                acc[0][0] += a.x * c.x; acc[0][1] += a.x * c.y; acc[0][2] += a.x * c.z; acc[0][3] += a.x * c.w;
                acc[1][0] += a.y * c.x; acc[1][1] += a.y * c.y; acc[1][2] += a.y * c.z; acc[1][3] += a.y * c.w;
                acc[2][0] += a.z * c.x; acc[2][1] += a.z * c.y; acc[2][2] += a.z * c.z; acc[2][3] += a.z * c.w;
                acc[3][0] += a.w * c.x; acc[3][1] += a.w * c.y; acc[3][2] += a.w * c.z; acc[3][3] += a.w * c.w;
            }
            __syncthreads();
        }
        #pragma unroll
        for (int p = 0; p < 4; p++)
            #pragma unroll
            for (int q = 0; q < 4; q++)
                atomicAdd(&g_SS[(ti * 4 + p) * KE + tj * 4 + q], acc[p][q]);
    } else {
        // ---------------- final: logits + log_softmax ----------------
        int bb = b - SP2B - SSB;
        for (int idx = t; idx < 512; idx += 256) {
            int c4 = idx >> 4, o = idx & 15;
            sWx[c4][o] = ((const float4*)g_Wc)[o * 32 + c4];
        }
        {
            int k4 = t >> 4, o = t & 15;
            sWa[k4][o] = ((const float4*)finW)[o * 80 + 64 + k4];
        }
        if (t < 16) sbo[t] = g_bc[t];
        __syncthreads();

        int n = bb * 16 + (t >> 4);
        int o = t & 15;
        const float4* x4 = (const float4*)x;
        const float4* S4 = (const float4*)g_S;
        float acc = sbo[o];
        #pragma unroll 8
        for (int c4 = 0; c4 < 32; c4++) {
            float4 xv = x4[(size_t)n * 32 + c4];
            float4 wv = sWx[c4][o];
            acc += xv.x * wv.x + xv.y * wv.y + xv.z * wv.z + xv.w * wv.w;
        }
        #pragma unroll 8
        for (int k4 = 0; k4 < 16; k4++) {
            float4 sv = S4[(size_t)n * 16 + k4];
            float4 wv = sWa[k4][o];
            acc += sv.x * wv.x + sv.y * wv.y + sv.z * wv.z + sv.w * wv.w;
        }
        float m = acc;
        #pragma unroll
        for (int d = 1; d < 16; d <<= 1) m = fmaxf(m, __shfl_xor_sync(0xffffffffu, m, d));
        float ex = expf(acc - m);
        float sum = ex;
        #pragma unroll
        for (int d = 1; d < 16; d <<= 1) sum += __shfl_xor_sync(0xffffffffu, sum, d);
        out[(size_t)n * 16 + o] = acc - m - logf(sum);
    }
}

// ================================================================ loss
__global__ void k_loss(float* __restrict__ out, int idx) {
    __shared__ double sh[256];
    __shared__ double dnrm;
    int t = threadIdx.x;
    double s = 0.0;
    for (int i = t; i < KE * KE; i += 256) { double v = (double)g_SS[i]; s += v * v; }
    sh[t] = s; __syncthreads();
    for (int off = 128; off >= 1; off >>= 1) { if (t < off) sh[t] += sh[t + off]; __syncthreads(); }
    if (t == 0) dnrm = sqrt(sh[0]);
    __syncthreads();
    double s2 = 0.0;
    for (int i = t; i < KE * KE; i += 256) {
        double v = (double)g_SS[i] / dnrm;
        if ((i >> 6) == (i & 63)) v -= 0.125;   // I / sqrt(64)
        s2 += v * v;
    }
    sh[t] = s2; __syncthreads();
    for (int off = 128; off >= 1; off >>= 1) { if (t < off) sh[t] += sh[t + off]; __syncthreads(); }
    if (t == 0) {
        double loss = -(g_cut / g_dt) + sqrt(sh[0]);
        out[idx] = (float)loss;
    }
}

// ================================================================ launch
extern "C" void kernel_launch(void* const* d_in, const int* in_sizes, int n_in,
                              void* d_out, int out_size) {
    const float* x     = (const float*)d_in[0];
    const int*   ei    = (const int*)  d_in[1];
    const float* MLPW  = (const float*)d_in[2];
    const float* MLPb  = (const float*)d_in[3];
    const float* mlpxW = (const float*)d_in[4];
    const float* mlpxb = (const float*)d_in[5];
    const float* finW  = (const float*)d_in[6];
    const float* finb  = (const float*)d_in[7];
    float* out = (float*)d_out;

    const int* row = ei;
    const int* col = ei + EE;
    const int nblk_scan = (NN + 1023) / 1024;   // 98

    void* degp = nullptr;
    cudaGetSymbolAddress(&degp, g_deg);
    cudaMemsetAsync(degp, 0, NN * sizeof(int));

    k_mega1<<<HIB + TRB + WCB, 256>>>(MLPW, col, finW, mlpxW, mlpxb, finb);
    k_scan1<<<nblk_scan, 256>>>();
    k_scan23<<<(NN + 255) / 256, 256>>>(nblk_scan);
    k_scatter<<<EE / 256, 256>>>(row, col);
    k_spmm1<<<NN / 8, 256>>>(MLPb);
    k_mega2<<<SP2B + SSB + FINB, 256>>>(x, finW, out);
    k_loss<<<1, 256>>>(out, out_size - 1);
}

// round 4
// speedup vs baseline: 1.6599x; 1.6599x over previous
#include <cuda_runtime.h>
#include <cuda_fp16.h>
#include <math.h>

#define NN 100000
#define EE 1600000
#define KE 64
#define INC 128
#define HID 256
#define OC 16

// ---- static device scratch ----
__device__ __half  g_Wh[(size_t)NN * KE];  // MLP_W^T fp16 [N,64]
__device__ float   g_S [(size_t)NN * KE];  // S fp32
__device__ __half  g_Sh[(size_t)NN * KE];  // S fp16 (SpMM2 gather)
__device__ int     g_deg[NN];
__device__ int     g_ptr[NN + 1];
__device__ int     g_pos[NN];
__device__ int     g_srt[EE];
__device__ int     g_bsum[128];
__device__ float   g_SS[KE * KE];
__device__ float   g_Wc[OC * INC];
__device__ float   g_bc[OC];
__device__ double  g_cut;
__device__ double  g_dt;
__device__ volatile unsigned g_bar;

// ---- software grid barrier: safe because grid <= guaranteed-resident blocks ----
__device__ __forceinline__ void gsync(unsigned target) {
    __syncthreads();
    if (threadIdx.x == 0) {
        __threadfence();
        atomicAdd((unsigned*)&g_bar, 1u);
        while (g_bar < target) __nanosleep(64);
        __threadfence();
    }
    __syncthreads();
}

__global__ void __launch_bounds__(256) k_persist(
    const float* __restrict__ W,        // MLP_W [64,N]
    const int*   __restrict__ row,
    const int*   __restrict__ col,
    const float* __restrict__ MLPb,
    const float* __restrict__ finW,
    const float* __restrict__ mlpxW,
    const float* __restrict__ mlpxb,
    const float* __restrict__ finb,
    const float* __restrict__ x,
    float*       __restrict__ out,
    int outIdx)
{
    const unsigned G = gridDim.x;
    const int bid = blockIdx.x;
    const int t   = threadIdx.x;
    const int tid = bid * 256 + t;
    const int stride = G * 256;

    __shared__ float  s_tile[32][33];
    __shared__ int    s_scan[256];
    __shared__ int    s_exc[128];
    __shared__ double s_red[8];
    __shared__ float4 s_rows[16][16];
    __shared__ float4 s_Wx[32][16];
    __shared__ float4 s_Wa[16][16];
    __shared__ float  s_bo[16];
    __shared__ double s_loss[256];
    __shared__ double s_dnrm;

    // ================= P0: hist | transpose->fp16 | wcomb | zero small =================
    if (bid == 0) {
        for (int i = t; i < KE * KE; i += 256) g_SS[i] = 0.f;
        if (t == 0) { g_cut = 0.0; g_dt = 0.0; }
    }
    for (int e = tid; e < EE; e += stride) atomicAdd(&g_deg[col[e]], 1);
    for (int tb = bid; tb < 6250; tb += (int)G) {
        int v0 = (tb % 3125) * 32, k0 = (tb / 3125) * 32;
        int tx = t & 31, ty = t >> 5;
        __syncthreads();
        #pragma unroll
        for (int r = ty; r < 32; r += 8)
            s_tile[r][tx] = W[(size_t)(k0 + r) * NN + v0 + tx];
        __syncthreads();
        #pragma unroll
        for (int r = ty; r < 32; r += 8)
            g_Wh[(size_t)(v0 + r) * KE + k0 + tx] = __float2half(s_tile[tx][r]);
    }
    for (int idx = tid; idx < OC * INC; idx += stride) {
        int o = idx >> 7, c = idx & 127;
        float s = 0.f;
        for (int h = 0; h < HID; h++) s += finW[o * 320 + h] * mlpxW[h * INC + c];
        g_Wc[idx] = s;
    }
    if (tid < OC) {
        float s = finb[tid];
        for (int h = 0; h < HID; h++) s += finW[tid * 320 + h] * mlpxb[h];
        g_bc[tid] = s;
    }
    gsync(1u * G);

    // ================= P1: per-chunk scan (98 chunks of 1024) =================
    for (int c = bid; c < 98; c += (int)G) {
        int base = c * 1024 + t * 4;
        int v0 = (base + 0 < NN) ? g_deg[base + 0] : 0;
        int v1 = (base + 1 < NN) ? g_deg[base + 1] : 0;
        int v2 = (base + 2 < NN) ? g_deg[base + 2] : 0;
        int v3 = (base + 3 < NN) ? g_deg[base + 3] : 0;
        int s = v0 + v1 + v2 + v3;
        s_scan[t] = s; __syncthreads();
        for (int off = 1; off < 256; off <<= 1) {
            int xv = (t >= off) ? s_scan[t - off] : 0;
            __syncthreads();
            s_scan[t] += xv;
            __syncthreads();
        }
        int run = s_scan[t] - s;
        if (t == 255) g_bsum[c] = s_scan[255];
        if (base + 0 < NN) g_ptr[base + 0] = run; run += v0;
        if (base + 1 < NN) g_ptr[base + 1] = run; run += v1;
        if (base + 2 < NN) g_ptr[base + 2] = run; run += v2;
        if (base + 3 < NN) g_ptr[base + 3] = run;
    }
    gsync(2u * G);

    // ================= P2: redundant block-sum scan + apply offsets =================
    {
        int v = (t < 98) ? g_bsum[t] : 0;
        if (t < 128) s_scan[t] = v;
        __syncthreads();
        for (int off = 1; off < 128; off <<= 1) {
            int xv = 0;
            if (t < 128 && t >= off) xv = s_scan[t - off];
            __syncthreads();
            if (t < 128) s_scan[t] += xv;
            __syncthreads();
        }
        if (t < 128) s_exc[t] = s_scan[t] - v;
        __syncthreads();
        for (int i = tid; i < NN; i += stride) {
            int p = g_ptr[i] + s_exc[i >> 10];
            g_ptr[i] = p;
            g_pos[i] = p;
        }
        if (tid == 0) g_ptr[NN] = EE;
    }
    gsync(3u * G);

    // ================= P3: scatter edges into CSR =================
    for (int e = tid; e < EE; e += stride) {
        int p = atomicAdd(&g_pos[col[e]], 1);
        g_srt[p] = row[e];
    }
    gsync(4u * G);

    // ================= P4: SpMM1 + softmax + deg_term (warp/node) =================
    {
        int gw = tid >> 5, l = t & 31, wl = t >> 5;
        int nw = G * 8;
        const __half2* F = (const __half2*)g_Wh;
        float2 b2 = __ldg(&((const float2*)MLPb)[l]);
        double ddt = 0.0;
        for (int w = gw; w < NN; w += nw) {
            int s = g_ptr[w], e = g_ptr[w + 1];
            float a0 = 0.f, a1 = 0.f;
            int i = s;
            for (; i + 4 <= e; i += 4) {
                int s0 = __ldg(&g_srt[i]),     s1 = __ldg(&g_srt[i + 1]);
                int s2 = __ldg(&g_srt[i + 2]), s3 = __ldg(&g_srt[i + 3]);
                float2 f0 = __half22float2(__ldg(&F[(size_t)s0 * 32 + l]));
                float2 f1 = __half22float2(__ldg(&F[(size_t)s1 * 32 + l]));
                float2 f2 = __half22float2(__ldg(&F[(size_t)s2 * 32 + l]));
                float2 f3 = __half22float2(__ldg(&F[(size_t)s3 * 32 + l]));
                a0 += (f0.x + f1.x) + (f2.x + f3.x);
                a1 += (f0.y + f1.y) + (f2.y + f3.y);
            }
            for (; i < e; i++) {
                int s0 = __ldg(&g_srt[i]);
                float2 f = __half22float2(__ldg(&F[(size_t)s0 * 32 + l]));
                a0 += f.x; a1 += f.y;
            }
            a0 += b2.x; a1 += b2.y;
            float m = fmaxf(a0, a1);
            #pragma unroll
            for (int d = 16; d >= 1; d >>= 1) m = fmaxf(m, __shfl_xor_sync(0xffffffffu, m, d));
            float e0 = expf(a0 - m), e1 = expf(a1 - m);
            float sum = e0 + e1;
            #pragma unroll
            for (int d = 16; d >= 1; d >>= 1) sum += __shfl_xor_sync(0xffffffffu, sum, d);
            float inv = 1.f / sum;
            float s0 = e0 * inv, s1 = e1 * inv;
            ((float2*)g_S)[(size_t)w * 32 + l] = make_float2(s0, s1);
            ((__half2*)g_Sh)[(size_t)w * 32 + l] = __floats2half2_rn(s0, s1);
            float ssq = s0 * s0 + s1 * s1;
            #pragma unroll
            for (int d = 16; d >= 1; d >>= 1) ssq += __shfl_xor_sync(0xffffffffu, ssq, d);
            if (l == 0) ddt += (double)(e - s) * (double)ssq;
        }
        __syncthreads();
        if (l == 0) s_red[wl] = ddt;
        __syncthreads();
        if (t == 0) {
            double a = 0.0;
            #pragma unroll
            for (int q = 0; q < 8; q++) a += s_red[q];
            atomicAdd(&g_dt, a);
        }
    }
    gsync(5u * G);

    // ================= P5: SpMM2 + cut (warp/node) =================
    {
        int gw = tid >> 5, l = t & 31, wl = t >> 5;
        int nw = G * 8;
        const __half2* F = (const __half2*)g_Sh;
        double dcut = 0.0;
        for (int w = gw; w < NN; w += nw) {
            int s = g_ptr[w], e = g_ptr[w + 1];
            float a0 = 0.f, a1 = 0.f;
            int i = s;
            for (; i + 4 <= e; i += 4) {
                int s0 = __ldg(&g_srt[i]),     s1 = __ldg(&g_srt[i + 1]);
                int s2 = __ldg(&g_srt[i + 2]), s3 = __ldg(&g_srt[i + 3]);
                float2 f0 = __half22float2(__ldg(&F[(size_t)s0 * 32 + l]));
                float2 f1 = __half22float2(__ldg(&F[(size_t)s1 * 32 + l]));
                float2 f2 = __half22float2(__ldg(&F[(size_t)s2 * 32 + l]));
                float2 f3 = __half22float2(__ldg(&F[(size_t)s3 * 32 + l]));
                a0 += (f0.x + f1.x) + (f2.x + f3.x);
                a1 += (f0.y + f1.y) + (f2.y + f3.y);
            }
            for (; i < e; i++) {
                int s0 = __ldg(&g_srt[i]);
                float2 f = __half22float2(__ldg(&F[(size_t)s0 * 32 + l]));
                a0 += f.x; a1 += f.y;
            }
            float2 sc = ((const float2*)g_S)[(size_t)w * 32 + l];
            float dot = a0 * sc.x + a1 * sc.y;
            #pragma unroll
            for (int d = 16; d >= 1; d >>= 1) dot += __shfl_xor_sync(0xffffffffu, dot, d);
            if (l == 0) dcut += (double)dot;
        }
        __syncthreads();
        if (l == 0) s_red[wl] = dcut;
        __syncthreads();
        if (t == 0) {
            double a = 0.0;
            #pragma unroll
            for (int q = 0; q < 8; q++) a += s_red[q];
            atomicAdd(&g_cut, a);
        }
    }
    gsync(6u * G);

    // ================= P6: SSmat (blocks < ssp) | final (rest) =================
    {
        int ssp = (G >= 512u) ? 256 : (int)(G / 2);
        if (bid < ssp) {
            int ti = t >> 4, tj = t & 15;
            float acc[4][4] = {};
            const float4* S4 = (const float4*)g_S;
            for (int rb = bid * 16; rb < NN; rb += ssp * 16) {
                __syncthreads();
                s_rows[t >> 4][t & 15] = S4[(size_t)(rb + (t >> 4)) * 16 + (t & 15)];
                __syncthreads();
                #pragma unroll 4
                for (int r = 0; r < 16; r++) {
                    float4 a = s_rows[r][ti];
                    float4 c = s_rows[r][tj];
                    acc[0][0] += a.x * c.x; acc[0][1] += a.x * c.y; acc[0][2] += a.x * c.z; acc[0][3] += a.x * c.w;
                    acc[1][0] += a.y * c.x; acc[1][1] += a.y * c.y; acc[1][2] += a.y * c.z; acc[1][3] += a.y * c.w;
                    acc[2][0] += a.z * c.x; acc[2][1] += a.z * c.y; acc[2][2] += a.z * c.z; acc[2][3] += a.z * c.w;
                    acc[3][0] += a.w * c.x; acc[3][1] += a.w * c.y; acc[3][2] += a.w * c.z; acc[3][3] += a.w * c.w;
                }
            }
            #pragma unroll
            for (int p = 0; p < 4; p++)
                #pragma unroll
                for (int q = 0; q < 4; q++)
                    atomicAdd(&g_SS[(ti * 4 + p) * KE + tj * 4 + q], acc[p][q]);
        } else {
            for (int idx = t; idx < 512; idx += 256) {
                int c4 = idx >> 4, o = idx & 15;
                s_Wx[c4][o] = ((const float4*)g_Wc)[o * 32 + c4];
            }
            {
                int k4 = t >> 4, o = t & 15;
                s_Wa[k4][o] = ((const float4*)finW)[o * 80 + 64 + k4];
            }
            if (t < 16) s_bo[t] = g_bc[t];
            __syncthreads();
            const float4* x4 = (const float4*)x;
            const float4* S4 = (const float4*)g_S;
            for (int g = bid - ssp; g < 6250; g += (int)G - ssp) {
                int n = g * 16 + (t >> 4);
                int o = t & 15;
                float acc = s_bo[o];
                #pragma unroll 8
                for (int c4 = 0; c4 < 32; c4++) {
                    float4 xv = x4[(size_t)n * 32 + c4];
                    float4 wv = s_Wx[c4][o];
                    acc += xv.x * wv.x + xv.y * wv.y + xv.z * wv.z + xv.w * wv.w;
                }
                #pragma unroll 8
                for (int k4 = 0; k4 < 16; k4++) {
                    float4 sv = S4[(size_t)n * 16 + k4];
                    float4 wv = s_Wa[k4][o];
                    acc += sv.x * wv.x + sv.y * wv.y + sv.z * wv.z + sv.w * wv.w;
                }
                float m = acc;
                #pragma unroll
                for (int d = 1; d < 16; d <<= 1) m = fmaxf(m, __shfl_xor_sync(0xffffffffu, m, d));
                float ex = expf(acc - m);
                float sum = ex;
                #pragma unroll
                for (int d = 1; d < 16; d <<= 1) sum += __shfl_xor_sync(0xffffffffu, sum, d);
                out[(size_t)n * 16 + o] = acc - m - logf(sum);
            }
        }
    }
    gsync(7u * G);

    // ================= P7: loss (block 0) =================
    if (bid == 0) {
        double s = 0.0;
        for (int i = t; i < KE * KE; i += 256) { double v = (double)g_SS[i]; s += v * v; }
        s_loss[t] = s; __syncthreads();
        for (int off = 128; off >= 1; off >>= 1) { if (t < off) s_loss[t] += s_loss[t + off]; __syncthreads(); }
        if (t == 0) s_dnrm = sqrt(s_loss[0]);
        __syncthreads();
        double s2 = 0.0;
        for (int i = t; i < KE * KE; i += 256) {
            double v = (double)g_SS[i] / s_dnrm;
            if ((i >> 6) == (i & 63)) v -= 0.125;   // I / sqrt(64)
            s2 += v * v;
        }
        s_loss[t] = s2; __syncthreads();
        for (int off = 128; off >= 1; off >>= 1) { if (t < off) s_loss[t] += s_loss[t + off]; __syncthreads(); }
        if (t == 0) {
            double loss = -(g_cut / g_dt) + sqrt(s_loss[0]);
            out[outIdx] = (float)loss;
        }
    }
}

// ================================================================ launch
extern "C" void kernel_launch(void* const* d_in, const int* in_sizes, int n_in,
                              void* d_out, int out_size) {
    const float* x     = (const float*)d_in[0];
    const int*   ei    = (const int*)  d_in[1];
    const float* MLPW  = (const float*)d_in[2];
    const float* MLPb  = (const float*)d_in[3];
    const float* mlpxW = (const float*)d_in[4];
    const float* mlpxb = (const float*)d_in[5];
    const float* finW  = (const float*)d_in[6];
    const float* finb  = (const float*)d_in[7];
    float* out = (float*)d_out;

    const int* row = ei;
    const int* col = ei + EE;

    int nb = 0;
    cudaOccupancyMaxActiveBlocksPerMultiprocessor(&nb, k_persist, 256, 0);
    if (nb <= 0) nb = 1;
    int smc = 0;
    cudaDeviceGetAttribute(&smc, cudaDevAttrMultiProcessorCount, 0);
    if (smc <= 0) smc = 148;
    unsigned G = (unsigned)(nb * smc);
    if (G > 2048u) G = 2048u;

    void* degp = nullptr;  cudaGetSymbolAddress(&degp, g_deg);
    void* barp = nullptr;  cudaGetSymbolAddress(&barp, g_bar);
    cudaMemsetAsync(degp, 0, NN * sizeof(int));
    cudaMemsetAsync(barp, 0, sizeof(unsigned));

    k_persist<<<G, 256>>>(MLPW, row, col, MLPb, finW, mlpxW, mlpxb, finb, x, out,
                          out_size - 1);
}